// round 4
// baseline (speedup 1.0000x reference)
#include <cuda_runtime.h>
#include <cstdint>

// ---------------------------------------------------------------------------
// Sparse CNN backbone, fp32.
// Conv layout: lane = output channel (L per group, G=32/L row-groups/warp),
// R rows per group per warp. Input rows gathered with group-uniform loads
// (1-2 wavefronts/instr instead of 32). Weights pre-paired in smem for
// fma.rn.f32x2 over input-channel pairs. BN stats fused into conv epilogue.
// ---------------------------------------------------------------------------

#define MAXN2 80000
#define MAXN4 13824

__device__ float g_xc[MAXN2 * 32];
__device__ float g_z1[MAXN2 * 32];
__device__ float g_z2[MAXN2 * 32];
__device__ float g_xt[MAXN2 * 32];
__device__ float g_y[MAXN4 * 64];
__device__ float g_part[1024 * 64 * 2];
__device__ float g_par[128];

typedef unsigned long long ull;

__device__ __forceinline__ ull packf2(float lo, float hi) {
    ull r;
    asm("mov.b64 %0, {%1, %2};" : "=l"(r) : "f"(lo), "f"(hi));
    return r;
}
__device__ __forceinline__ void fma2(ull& d, ull a, ull b) {
    asm("fma.rn.f32x2 %0, %1, %2, %0;" : "+l"(d) : "l"(a), "l"(b));
}
__device__ __forceinline__ float unpack_sum(ull a) {
    float lo, hi;
    asm("mov.b64 {%0, %1}, %2;" : "=f"(lo), "=f"(hi) : "l"(a));
    return lo + hi;
}

// ---------------------------------------------------------------------------
// Generic conv. CIN in {32,64}. L = channels per lane-group (lane%L = ch),
// G = 32/L row groups per warp, R rows per group. COUT sliced by blockIdx.y.
// STATS: write per-block per-channel (sum,sumsq) partials to part.
// ---------------------------------------------------------------------------
template <int CIN, int L, int R, bool STATS>
__global__ __launch_bounds__(512, 2) void conv_s(
    const float* __restrict__ feats, const float* __restrict__ W,
    const int* __restrict__ in_map, int n_in, int n_out, int COUT,
    float* __restrict__ out, float* __restrict__ part) {
    constexpr int G = 32 / L;
    constexpr int CP = CIN / 2;
    extern __shared__ ull sW[];  // [27][CP][L] paired weights

    const int tid = threadIdx.x;
    const int lane = tid & 31;
    const int w = tid >> 5;
    const int ch = lane % L;
    const int g = lane / L;
    const int yoff = blockIdx.y * L;

    // Stage weights, paired over input channels: sW[k][cp][ch]={W[2cp],W[2cp+1]}
    {
        const int quads = 27 * CP * (L / 4);
        for (int i = tid; i < quads; i += 512) {
            int q = i % (L / 4);
            int rem = i / (L / 4);
            int cp = rem % CP;
            int k = rem / CP;
            const float* base = W + ((size_t)(k * CIN + 2 * cp)) * COUT + yoff + 4 * q;
            float4 lo = *reinterpret_cast<const float4*>(base);
            float4 hi = *reinterpret_cast<const float4*>(base + COUT);
            ull* dst = sW + ((size_t)(k * CP + cp)) * L + 4 * q;
            dst[0] = packf2(lo.x, hi.x);
            dst[1] = packf2(lo.y, hi.y);
            dst[2] = packf2(lo.z, hi.z);
            dst[3] = packf2(lo.w, hi.w);
        }
    }
    __syncthreads();

    const int row0 = blockIdx.x * (16 * G * R) + (w * G + g) * R;

    ull acc[R];
#pragma unroll
    for (int r = 0; r < R; r++) acc[r] = 0ull;

    for (int k = 0; k < 27; k++) {
        int idx[R];
        bool anyv = false;
        const int* mp = in_map + (size_t)k * n_out;
#pragma unroll
        for (int r = 0; r < R; r++) {
            idx[r] = (row0 + r < n_out) ? __ldg(&mp[row0 + r]) : n_in;
            anyv |= (idx[r] < n_in);
        }
        if (__ballot_sync(0xffffffffu, anyv) == 0u) continue;

#pragma unroll
        for (int cc = 0; cc < CIN / 4; cc++) {
            ulonglong2 v[R];
#pragma unroll
            for (int r = 0; r < R; r++) {
                if (idx[r] < n_in)
                    v[r] = *reinterpret_cast<const ulonglong2*>(
                        feats + (size_t)idx[r] * CIN + 4 * cc);
                else
                    v[r] = make_ulonglong2(0ull, 0ull);
            }
            const ull wA = sW[((size_t)(k * CP + 2 * cc)) * L + ch];
            const ull wB = sW[((size_t)(k * CP + 2 * cc + 1)) * L + ch];
#pragma unroll
            for (int r = 0; r < R; r++) {
                fma2(acc[r], v[r].x, wA);
                fma2(acc[r], v[r].y, wB);
            }
        }
    }

    // Epilogue: write outputs, collect stats
    float vals[R];
    float s = 0.f, ss = 0.f;
#pragma unroll
    for (int r = 0; r < R; r++) {
        vals[r] = unpack_sum(acc[r]);
        if (row0 + r < n_out) {
            out[(size_t)(row0 + r) * COUT + yoff + ch] = vals[r];
            if (STATS) {
                s += vals[r];
                ss += vals[r] * vals[r];
            }
        }
    }
    if (STATS) {
        if (G == 2) {
            s += __shfl_down_sync(0xffffffffu, s, 16);
            ss += __shfl_down_sync(0xffffffffu, ss, 16);
        }
        __syncthreads();  // all warps done reading sW
        float* sp = reinterpret_cast<float*>(sW);
        if (g == 0) {
            sp[(w * L + ch) * 2] = s;
            sp[(w * L + ch) * 2 + 1] = ss;
        }
        __syncthreads();
        if (tid < L) {
            float S = 0.f, Q = 0.f;
#pragma unroll
            for (int i = 0; i < 16; i++) {
                S += sp[(i * L + tid) * 2];
                Q += sp[(i * L + tid) * 2 + 1];
            }
            part[((size_t)blockIdx.x * 64 + yoff + tid) * 2] = S;
            part[((size_t)blockIdx.x * 64 + yoff + tid) * 2 + 1] = Q;
        }
    }
}

// ---------------------------------------------------------------------------
// First conv: CIN=4 (geo ++ col), COUT=32, K=125, ReLU out. lane=channel.
// ---------------------------------------------------------------------------
template <int R>
__global__ __launch_bounds__(512, 2) void conv1_s(
    const float* __restrict__ geo, const float* __restrict__ col,
    const float* __restrict__ W, const int* __restrict__ in_map, int n_in,
    int n_out, float* __restrict__ out) {
    extern __shared__ ull sW[];  // [125][2][32]
    const int tid = threadIdx.x;
    const int lane = tid & 31;
    const int w = tid >> 5;

    {
        const int quads = 125 * 2 * 8;
        for (int i = tid; i < quads; i += 512) {
            int q = i % 8;
            int rem = i / 8;
            int cp = rem % 2;
            int k = rem / 2;
            const float* base = W + ((size_t)(k * 4 + 2 * cp)) * 32 + 4 * q;
            float4 lo = *reinterpret_cast<const float4*>(base);
            float4 hi = *reinterpret_cast<const float4*>(base + 32);
            ull* dst = sW + ((size_t)(k * 2 + cp)) * 32 + 4 * q;
            dst[0] = packf2(lo.x, hi.x);
            dst[1] = packf2(lo.y, hi.y);
            dst[2] = packf2(lo.z, hi.z);
            dst[3] = packf2(lo.w, hi.w);
        }
    }
    __syncthreads();

    const int row0 = blockIdx.x * (16 * R) + w * R;
    ull acc[R];
#pragma unroll
    for (int r = 0; r < R; r++) acc[r] = 0ull;

    for (int k = 0; k < 125; k++) {
        int idx[R];
        bool anyv = false;
        const int* mp = in_map + (size_t)k * n_out;
#pragma unroll
        for (int r = 0; r < R; r++) {
            idx[r] = (row0 + r < n_out) ? __ldg(&mp[row0 + r]) : n_in;
            anyv |= (idx[r] < n_in);
        }
        if (!anyv) continue;  // warp-uniform (G=1)

        const ull wA = sW[(size_t)(k * 2) * 32 + lane];
        const ull wB = sW[(size_t)(k * 2 + 1) * 32 + lane];
#pragma unroll
        for (int r = 0; r < R; r++) {
            if (idx[r] < n_in) {
                float f0 = __ldg(&geo[idx[r]]);
                float c0 = __ldg(&col[(size_t)idx[r] * 3]);
                float c1 = __ldg(&col[(size_t)idx[r] * 3 + 1]);
                float c2 = __ldg(&col[(size_t)idx[r] * 3 + 2]);
                fma2(acc[r], packf2(f0, c0), wA);
                fma2(acc[r], packf2(c1, c2), wB);
            }
        }
    }
#pragma unroll
    for (int r = 0; r < R; r++) {
        if (row0 + r < n_out)
            out[(size_t)(row0 + r) * 32 + lane] = fmaxf(unpack_sum(acc[r]), 0.f);
    }
}

// ---------------------------------------------------------------------------
// Fold per-block partials -> scale/shift. part layout: [nblk][64][2].
// ---------------------------------------------------------------------------
__global__ __launch_bounds__(256) void bn_reduce(
    const float* __restrict__ part, int nblk, int C, int n,
    const float* __restrict__ g, const float* __restrict__ b,
    float* __restrict__ params) {
    __shared__ float ss[256], sq[256];
    const int t = threadIdx.x;
    const int P = 256 / C;
    const int c = t % C, r = t / C;
    float s = 0.f, q = 0.f;
    for (int i = r; i < nblk; i += P) {
        s += part[((size_t)i * 64 + c) * 2];
        q += part[((size_t)i * 64 + c) * 2 + 1];
    }
    ss[t] = s;
    sq[t] = q;
    __syncthreads();
    for (int o = P / 2; o >= 1; o >>= 1) {
        if (r < o) {
            ss[t] += ss[t + o * C];
            sq[t] += sq[t + o * C];
        }
        __syncthreads();
    }
    if (r == 0) {
        float inv_n = 1.f / (float)n;
        float mu = ss[t] * inv_n;
        float var = sq[t] * inv_n - mu * mu;
        float sc = g[c] * rsqrtf(var + 1e-5f);
        params[c] = sc;
        params[C + c] = b[c] - mu * sc;
    }
}

// xt = relu(z*scale + shift)
__global__ __launch_bounds__(256) void bn_apply(
    const float4* __restrict__ z, const float* __restrict__ par,
    float4* __restrict__ out, int n, int C) {
    int total = n * C / 4;
    for (int i = blockIdx.x * 256 + threadIdx.x; i < total; i += gridDim.x * 256) {
        int cb = (i * 4) % C;
        float4 v = z[i];
        v.x = fmaxf(v.x * par[cb] + par[C + cb], 0.f);
        v.y = fmaxf(v.y * par[cb + 1] + par[C + cb + 1], 0.f);
        v.z = fmaxf(v.z * par[cb + 2] + par[C + cb + 2], 0.f);
        v.w = fmaxf(v.w * par[cb + 3] + par[C + cb + 3], 0.f);
        out[i] = v;
    }
}

// out = relu(z*scale + shift + res)
__global__ __launch_bounds__(256) void bn_res_relu(
    const float4* __restrict__ z, const float* __restrict__ par,
    const float4* __restrict__ res, float4* __restrict__ out, int n, int C) {
    int total = n * C / 4;
    for (int i = blockIdx.x * 256 + threadIdx.x; i < total; i += gridDim.x * 256) {
        int cb = (i * 4) % C;
        float4 v = z[i];
        float4 r = res[i];
        v.x = fmaxf(v.x * par[cb] + par[C + cb] + r.x, 0.f);
        v.y = fmaxf(v.y * par[cb + 1] + par[C + cb + 1] + r.y, 0.f);
        v.z = fmaxf(v.z * par[cb + 2] + par[C + cb + 2] + r.z, 0.f);
        v.w = fmaxf(v.w * par[cb + 3] + par[C + cb + 3] + r.w, 0.f);
        out[i] = v;
    }
}

// ---------------------------------------------------------------------------
extern "C" void kernel_launch(void* const* d_in, const int* in_sizes, int n_in,
                              void* d_out, int out_size) {
    const float* x_geo = (const float*)d_in[0];
    const float* x_col = (const float*)d_in[1];
    const float* w0 = (const float*)d_in[2];
    const float* w_e1 = (const float*)d_in[3];
    const float* g_e1 = (const float*)d_in[4];
    const float* b_e1 = (const float*)d_in[5];
    const float* w2 = (const float*)d_in[6];
    const float* w_e2 = (const float*)d_in[7];
    const float* g_e2 = (const float*)d_in[8];
    const float* b_e2 = (const float*)d_in[9];
    const int* m1_in = (const int*)d_in[10];
    const int* m2_in = (const int*)d_in[12];
    const int* m3_in = (const int*)d_in[14];
    const int* m4_in = (const int*)d_in[16];

    const int N = in_sizes[0];
    const int n2 = in_sizes[10] / 125;
    const int n4 = in_sizes[14] / 27;

    float *xc, *z1, *z2, *xt, *yb, *part, *par;
    cudaGetSymbolAddress((void**)&xc, g_xc);
    cudaGetSymbolAddress((void**)&z1, g_z1);
    cudaGetSymbolAddress((void**)&z2, g_z2);
    cudaGetSymbolAddress((void**)&xt, g_xt);
    cudaGetSymbolAddress((void**)&yb, g_y);
    cudaGetSymbolAddress((void**)&part, g_part);
    cudaGetSymbolAddress((void**)&par, g_par);

    constexpr int R = 4;
    const int SM1 = 125 * 2 * 32 * 8;       // 64000
    const int SME1 = 27 * 16 * 32 * 8;      // 110592 (CIN=32, L=32)
    const int SMC2 = 27 * 16 * 16 * 8;      // 55296  (CIN=32, L=16)
    const int SME2 = 27 * 32 * 16 * 8;      // 110592 (CIN=64, L=16)
    cudaFuncSetAttribute(conv1_s<R>, cudaFuncAttributeMaxDynamicSharedMemorySize, SM1);
    cudaFuncSetAttribute(conv_s<32, 32, R, true>, cudaFuncAttributeMaxDynamicSharedMemorySize, SME1);
    cudaFuncSetAttribute(conv_s<32, 16, R, false>, cudaFuncAttributeMaxDynamicSharedMemorySize, SMC2);
    cudaFuncSetAttribute(conv_s<64, 16, R, true>, cudaFuncAttributeMaxDynamicSharedMemorySize, SME2);

    // rows per block: conv1/enc1 (G=1): 16*R = 64; conv2/enc2 (G=2): 128
    const int gx1 = (n2 + 63) / 64;
    const dim3 ge1(gx1, 1);
    const int gx4 = (n4 + 127) / 128;
    const dim3 gc2(gx4, 4), ge2(gx4, 4);
    const int eg2 = (n2 * 32 / 4 + 255) / 256;
    const int eg4 = (n4 * 64 / 4 + 255) / 256;

    // conv1 (k5 s2, 4->32) + ReLU
    conv1_s<R><<<gx1, 512, SM1>>>(x_geo, x_col, w0, m1_in, N, n2, xc);

    // enc1: 2 BasicBlocks, 32ch
    for (int i = 0; i < 2; i++) {
        const float* wA = w_e1 + (size_t)(i * 2 + 0) * 27 * 32 * 32;
        const float* wB = w_e1 + (size_t)(i * 2 + 1) * 27 * 32 * 32;
        conv_s<32, 32, R, true><<<ge1, 512, SME1>>>(xc, wA, m2_in, n2, n2, 32, z1, part);
        bn_reduce<<<1, 256>>>(part, gx1, 32, n2,
                              g_e1 + (size_t)(i * 2) * 32, b_e1 + (size_t)(i * 2) * 32, par);
        bn_apply<<<eg2 < 2048 ? eg2 : 2048, 256>>>((const float4*)z1, par, (float4*)xt, n2, 32);
        conv_s<32, 32, R, true><<<ge1, 512, SME1>>>(xt, wB, m2_in, n2, n2, 32, z2, part);
        bn_reduce<<<1, 256>>>(part, gx1, 32, n2,
                              g_e1 + (size_t)(i * 2 + 1) * 32, b_e1 + (size_t)(i * 2 + 1) * 32, par);
        bn_res_relu<<<eg2 < 2048 ? eg2 : 2048, 256>>>(
            (const float4*)z2, par, (const float4*)xc, (float4*)xc, n2, 32);
    }

    // conv2 (32 -> 64, onto stride-4 coords)
    conv_s<32, 16, R, false><<<gc2, 512, SMC2>>>(xc, w2, m3_in, n2, n4, 64, yb, nullptr);

    // enc2: 2 BasicBlocks, 64ch
    for (int i = 0; i < 2; i++) {
        const float* wA = w_e2 + (size_t)(i * 2 + 0) * 27 * 64 * 64;
        const float* wB = w_e2 + (size_t)(i * 2 + 1) * 27 * 64 * 64;
        conv_s<64, 16, R, true><<<ge2, 512, SME2>>>(yb, wA, m4_in, n4, n4, 64, z1, part);
        bn_reduce<<<1, 256>>>(part, gx4, 64, n4,
                              g_e2 + (size_t)(i * 2) * 64, b_e2 + (size_t)(i * 2) * 64, par);
        bn_apply<<<eg4 < 2048 ? eg4 : 2048, 256>>>((const float4*)z1, par, (float4*)xt, n4, 64);
        conv_s<64, 16, R, true><<<ge2, 512, SME2>>>(xt, wB, m4_in, n4, n4, 64, z2, part);
        bn_reduce<<<1, 256>>>(part, gx4, 64, n4,
                              g_e2 + (size_t)(i * 2 + 1) * 64, b_e2 + (size_t)(i * 2 + 1) * 64, par);
        float* dst = (i == 1) ? (float*)d_out : yb;
        bn_res_relu<<<eg4 < 2048 ? eg4 : 2048, 256>>>(
            (const float4*)z2, par, (const float4*)yb, (float4*)dst, n4, 64);
    }
}

// round 5
// speedup vs baseline: 1.2487x; 1.2487x over previous
#include <cuda_runtime.h>
#include <cstdint>

// ---------------------------------------------------------------------------
// Sparse CNN backbone, fp32. Thread = 1 row x SLICE out channels; all tap
// weights staged once in <=56KB smem (3 CTAs/SM); BN stats fused in epilogue.
// ---------------------------------------------------------------------------

#define MAXN2 80000
#define MAXN4 13824

__device__ float g_xc[MAXN2 * 32];
__device__ float g_z1[MAXN2 * 32];
__device__ float g_z2[MAXN2 * 32];
__device__ float g_y[MAXN4 * 64];
__device__ float g_part[1024 * 64 * 2];
__device__ float g_par[128];

typedef unsigned long long ull;

__device__ __forceinline__ ull pack2(float x) {
    ull r;
    asm("mov.b64 %0, {%1, %1};" : "=l"(r) : "f"(x));
    return r;
}
__device__ __forceinline__ void fma2(ull& d, ull a, ull b) {
    asm("fma.rn.f32x2 %0, %1, %2, %0;" : "+l"(d) : "l"(a), "l"(b));
}

// ---------------------------------------------------------------------------
// Conv: thread = 1 output row x SLICE channels (blockIdx.y slices COUT).
// TIN: apply relu(x*sc+sh) to gathered rows (folds previous BN+ReLU).
// STATS: per-block per-channel (sum,sumsq) partials -> part[bx][64][2].
// ---------------------------------------------------------------------------
template <int CIN, int SLICE, bool TIN, bool STATS>
__global__ __launch_bounds__(256, 3) void conv_t(
    const float* __restrict__ feats, const float* __restrict__ W,
    const int* __restrict__ in_map, const float* __restrict__ bnp,
    int n_in, int n_out, int COUT, float* __restrict__ out,
    float* __restrict__ part) {
    extern __shared__ float sm[];
    float* sW = sm;                         // 27*CIN*SLICE
    float* sSc = sm + 27 * CIN * SLICE;     // CIN (TIN only)
    float* sSh = sSc + CIN;

    const int tid = threadIdx.x;
    const int yoff = blockIdx.y * SLICE;
    constexpr int WV = SLICE / 4;

    for (int i = tid; i < 27 * CIN * WV; i += 256) {
        int r = i / WV, c = (i % WV) * 4;
        reinterpret_cast<float4*>(sW)[i] =
            *reinterpret_cast<const float4*>(W + (size_t)r * COUT + yoff + c);
    }
    if (TIN) {
        if (tid < CIN) sSc[tid] = bnp[tid];
        else if (tid < 2 * CIN) sSh[tid - CIN] = bnp[tid];
    }
    __syncthreads();

    const int row = blockIdx.x * 256 + tid;
    const bool rowok = row < n_out;

    ull acc[SLICE / 2];
#pragma unroll
    for (int i = 0; i < SLICE / 2; i++) acc[i] = 0ull;

    int idxn = rowok ? __ldg(&in_map[row]) : n_in;
    for (int k = 0; k < 27; k++) {
        int idx = idxn;
        if (k + 1 < 27)
            idxn = rowok ? __ldg(&in_map[(size_t)(k + 1) * n_out + row]) : n_in;
        if (idx >= n_in) continue;

        const float4* f4 = reinterpret_cast<const float4*>(feats + (size_t)idx * CIN);
        const float* wk = sW + k * CIN * SLICE;
#pragma unroll
        for (int cc = 0; cc < CIN / 8; cc++) {
            float f[8];
            float4 a = __ldg(&f4[2 * cc]), b = __ldg(&f4[2 * cc + 1]);
            f[0] = a.x; f[1] = a.y; f[2] = a.z; f[3] = a.w;
            f[4] = b.x; f[5] = b.y; f[6] = b.z; f[7] = b.w;
            if (TIN) {
#pragma unroll
                for (int j = 0; j < 8; j++)
                    f[j] = fmaxf(f[j] * sSc[8 * cc + j] + sSh[8 * cc + j], 0.f);
            }
#pragma unroll
            for (int j = 0; j < 8; j++) {
                ull a2 = pack2(f[j]);
                const ulonglong2* wr =
                    reinterpret_cast<const ulonglong2*>(wk + (8 * cc + j) * SLICE);
#pragma unroll
                for (int p = 0; p < SLICE / 4; p++) {
                    ulonglong2 w = wr[p];
                    fma2(acc[2 * p], a2, w.x);
                    fma2(acc[2 * p + 1], a2, w.y);
                }
            }
        }
    }

    float res[SLICE];
#pragma unroll
    for (int p = 0; p < SLICE / 2; p++) {
        float2 v = *reinterpret_cast<float2*>(&acc[p]);
        res[2 * p] = v.x;
        res[2 * p + 1] = v.y;
    }
    if (rowok) {
        float* op = out + (size_t)row * COUT + yoff;
#pragma unroll
        for (int i = 0; i < WV; i++)
            reinterpret_cast<float4*>(op)[i] = reinterpret_cast<float4*>(res)[i];
    }

    if (STATS) {
        __syncthreads();  // done with sW
        float* sv = sm;                 // 256*SLICE
        float* sq = sm + 256 * SLICE;   // 256*SLICE
#pragma unroll
        for (int s = 0; s < SLICE; s++) {
            float v = rowok ? res[s] : 0.f;
            sv[tid * SLICE + s] = v;
            sq[tid * SLICE + s] = v * v;
        }
        __syncthreads();
        constexpr int P = 256 / SLICE;
        const int c = tid % SLICE, g = tid / SLICE;
        float S = 0.f, Q = 0.f;
        for (int r = g; r < 256; r += P) {
            S += sv[r * SLICE + c];
            Q += sq[r * SLICE + c];
        }
        __syncthreads();
        sv[g * SLICE + c] = S;
        sq[g * SLICE + c] = Q;
        __syncthreads();
        if (tid < SLICE) {
            float S2 = 0.f, Q2 = 0.f;
#pragma unroll
            for (int r = 0; r < P; r++) {
                S2 += sv[r * SLICE + tid];
                Q2 += sq[r * SLICE + tid];
            }
            part[((size_t)blockIdx.x * 64 + yoff + tid) * 2] = S2;
            part[((size_t)blockIdx.x * 64 + yoff + tid) * 2 + 1] = Q2;
        }
    }
}

// ---------------------------------------------------------------------------
// First conv: CIN=4 (geo ++ col), COUT=32, K=125, ReLU out.
// ---------------------------------------------------------------------------
__global__ __launch_bounds__(256, 3) void conv1_k(
    const float* __restrict__ geo, const float* __restrict__ col,
    const float* __restrict__ W, const int* __restrict__ in_map, int n_in,
    int n_out, float* __restrict__ out) {
    extern __shared__ float sm[];
    const int tid = threadIdx.x;
    for (int i = tid; i < 125 * 32; i += 256)
        reinterpret_cast<float4*>(sm)[i] = reinterpret_cast<const float4*>(W)[i];
    __syncthreads();

    const int row = blockIdx.x * 256 + tid;
    if (row >= n_out) return;

    ull acc[16];
#pragma unroll
    for (int i = 0; i < 16; i++) acc[i] = 0ull;

    int idxn = __ldg(&in_map[row]);
    for (int k = 0; k < 125; k++) {
        int idx = idxn;
        if (k + 1 < 125) idxn = __ldg(&in_map[(size_t)(k + 1) * n_out + row]);
        if (idx >= n_in) continue;

        float fr[4];
        fr[0] = __ldg(&geo[idx]);
        fr[1] = __ldg(&col[(size_t)idx * 3]);
        fr[2] = __ldg(&col[(size_t)idx * 3 + 1]);
        fr[3] = __ldg(&col[(size_t)idx * 3 + 2]);
        const float* wk = sm + k * 128;
#pragma unroll
        for (int c = 0; c < 4; c++) {
            ull a2 = pack2(fr[c]);
            const ulonglong2* wrow = reinterpret_cast<const ulonglong2*>(wk + c * 32);
#pragma unroll
            for (int p = 0; p < 8; p++) {
                ulonglong2 w = wrow[p];
                fma2(acc[2 * p], a2, w.x);
                fma2(acc[2 * p + 1], a2, w.y);
            }
        }
    }
    float res[32];
#pragma unroll
    for (int p = 0; p < 16; p++) {
        float2 v = *reinterpret_cast<float2*>(&acc[p]);
        res[2 * p] = fmaxf(v.x, 0.f);
        res[2 * p + 1] = fmaxf(v.y, 0.f);
    }
    float* op = out + (size_t)row * 32;
#pragma unroll
    for (int i = 0; i < 8; i++)
        reinterpret_cast<float4*>(op)[i] = reinterpret_cast<float4*>(res)[i];
}

// ---------------------------------------------------------------------------
// Fold per-block partials -> scale/shift. part layout [nblk][64][2].
// ---------------------------------------------------------------------------
__global__ __launch_bounds__(256) void bn_reduce(
    const float* __restrict__ part, int nblk, int C, int n,
    const float* __restrict__ g, const float* __restrict__ b,
    float* __restrict__ params) {
    __shared__ float ss[256], sq[256];
    const int t = threadIdx.x;
    const int P = 256 / C;
    const int c = t % C, r = t / C;
    float s = 0.f, q = 0.f;
    for (int i = r; i < nblk; i += P) {
        s += part[((size_t)i * 64 + c) * 2];
        q += part[((size_t)i * 64 + c) * 2 + 1];
    }
    ss[t] = s;
    sq[t] = q;
    __syncthreads();
    for (int o = P / 2; o >= 1; o >>= 1) {
        if (r < o) {
            ss[t] += ss[t + o * C];
            sq[t] += sq[t + o * C];
        }
        __syncthreads();
    }
    if (r == 0) {
        float inv_n = 1.f / (float)n;
        float mu = ss[t] * inv_n;
        float var = sq[t] * inv_n - mu * mu;
        float sc = g[c] * rsqrtf(var + 1e-5f);
        params[c] = sc;
        params[C + c] = b[c] - mu * sc;
    }
}

// out = relu(z*scale + shift + res)
__global__ __launch_bounds__(256) void bn_res_relu(
    const float4* __restrict__ z, const float* __restrict__ par,
    const float4* __restrict__ res, float4* __restrict__ out, int n, int C) {
    int total = n * C / 4;
    for (int i = blockIdx.x * 256 + threadIdx.x; i < total; i += gridDim.x * 256) {
        int cb = (i * 4) % C;
        float4 v = z[i];
        float4 r = res[i];
        v.x = fmaxf(v.x * par[cb] + par[C + cb] + r.x, 0.f);
        v.y = fmaxf(v.y * par[cb + 1] + par[C + cb + 1] + r.y, 0.f);
        v.z = fmaxf(v.z * par[cb + 2] + par[C + cb + 2] + r.z, 0.f);
        v.w = fmaxf(v.w * par[cb + 3] + par[C + cb + 3] + r.w, 0.f);
        out[i] = v;
    }
}

// ---------------------------------------------------------------------------
extern "C" void kernel_launch(void* const* d_in, const int* in_sizes, int n_in,
                              void* d_out, int out_size) {
    const float* x_geo = (const float*)d_in[0];
    const float* x_col = (const float*)d_in[1];
    const float* w0 = (const float*)d_in[2];
    const float* w_e1 = (const float*)d_in[3];
    const float* g_e1 = (const float*)d_in[4];
    const float* b_e1 = (const float*)d_in[5];
    const float* w2 = (const float*)d_in[6];
    const float* w_e2 = (const float*)d_in[7];
    const float* g_e2 = (const float*)d_in[8];
    const float* b_e2 = (const float*)d_in[9];
    const int* m1_in = (const int*)d_in[10];
    const int* m2_in = (const int*)d_in[12];
    const int* m3_in = (const int*)d_in[14];
    const int* m4_in = (const int*)d_in[16];

    const int N = in_sizes[0];
    const int n2 = in_sizes[10] / 125;
    const int n4 = in_sizes[14] / 27;

    float *xc, *z1, *z2, *yb, *part, *par;
    cudaGetSymbolAddress((void**)&xc, g_xc);
    cudaGetSymbolAddress((void**)&z1, g_z1);
    cudaGetSymbolAddress((void**)&z2, g_z2);
    cudaGetSymbolAddress((void**)&yb, g_y);
    cudaGetSymbolAddress((void**)&part, g_part);
    cudaGetSymbolAddress((void**)&par, g_par);

    const int SM1 = 125 * 4 * 32 * 4;                 // 64000
    const int SME1 = (27 * 32 * 16 + 64) * 4;         // 55552 (CIN32, SLICE16)
    const int SMC2 = 27 * 32 * 8 * 4;                 // 27648 (CIN32, SLICE8)
    const int SME2 = (27 * 64 * 8 + 128) * 4;         // 55808 (CIN64, SLICE8)
    cudaFuncSetAttribute(conv1_k, cudaFuncAttributeMaxDynamicSharedMemorySize, SM1);
    cudaFuncSetAttribute(conv_t<32, 16, false, true>, cudaFuncAttributeMaxDynamicSharedMemorySize, SME1);
    cudaFuncSetAttribute(conv_t<32, 16, true, true>, cudaFuncAttributeMaxDynamicSharedMemorySize, SME1);
    cudaFuncSetAttribute(conv_t<32, 8, false, false>, cudaFuncAttributeMaxDynamicSharedMemorySize, SMC2);
    cudaFuncSetAttribute(conv_t<64, 8, false, true>, cudaFuncAttributeMaxDynamicSharedMemorySize, SME2);
    cudaFuncSetAttribute(conv_t<64, 8, true, true>, cudaFuncAttributeMaxDynamicSharedMemorySize, SME2);

    const int gx2 = (n2 + 255) / 256;
    const int gx4 = (n4 + 255) / 256;
    const dim3 ge1(gx2, 2);    // 32 out ch, SLICE 16
    const dim3 gc2(gx4, 8);    // 64 out ch, SLICE 8
    const dim3 ge2(gx4, 8);
    const int eg2 = (n2 * 32 / 4 + 255) / 256;
    const int eg4 = (n4 * 64 / 4 + 255) / 256;

    // conv1 (k5 s2, 4->32) + ReLU
    conv1_k<<<gx2, 256, SM1>>>(x_geo, x_col, w0, m1_in, N, n2, xc);

    // enc1: 2 BasicBlocks, 32ch
    for (int i = 0; i < 2; i++) {
        const float* wA = w_e1 + (size_t)(i * 2 + 0) * 27 * 32 * 32;
        const float* wB = w_e1 + (size_t)(i * 2 + 1) * 27 * 32 * 32;
        conv_t<32, 16, false, true><<<ge1, 256, SME1>>>(xc, wA, m2_in, nullptr, n2, n2, 32, z1, part);
        bn_reduce<<<1, 256>>>(part, gx2, 32, n2,
                              g_e1 + (size_t)(i * 2) * 32, b_e1 + (size_t)(i * 2) * 32, par);
        conv_t<32, 16, true, true><<<ge1, 256, SME1>>>(z1, wB, m2_in, par, n2, n2, 32, z2, part);
        bn_reduce<<<1, 256>>>(part, gx2, 32, n2,
                              g_e1 + (size_t)(i * 2 + 1) * 32, b_e1 + (size_t)(i * 2 + 1) * 32, par);
        bn_res_relu<<<eg2 < 2048 ? eg2 : 2048, 256>>>(
            (const float4*)z2, par, (const float4*)xc, (float4*)xc, n2, 32);
    }

    // conv2 (32 -> 64, onto stride-4 coords)
    conv_t<32, 8, false, false><<<gc2, 256, SMC2>>>(xc, w2, m3_in, nullptr, n2, n4, 64, yb, nullptr);

    // enc2: 2 BasicBlocks, 64ch
    for (int i = 0; i < 2; i++) {
        const float* wA = w_e2 + (size_t)(i * 2 + 0) * 27 * 64 * 64;
        const float* wB = w_e2 + (size_t)(i * 2 + 1) * 27 * 64 * 64;
        conv_t<64, 8, false, true><<<ge2, 256, SME2>>>(yb, wA, m4_in, nullptr, n4, n4, 64, z1, part);
        bn_reduce<<<1, 256>>>(part, gx4, 64, n4,
                              g_e2 + (size_t)(i * 2) * 64, b_e2 + (size_t)(i * 2) * 64, par);
        conv_t<64, 8, true, true><<<ge2, 256, SME2>>>(z1, wB, m4_in, par, n4, n4, 64, z2, part);
        bn_reduce<<<1, 256>>>(part, gx4, 64, n4,
                              g_e2 + (size_t)(i * 2 + 1) * 64, b_e2 + (size_t)(i * 2 + 1) * 64, par);
        float* dst = (i == 1) ? (float*)d_out : yb;
        bn_res_relu<<<eg4 < 2048 ? eg4 : 2048, 256>>>(
            (const float4*)z2, par, (const float4*)yb, (float4*)dst, n4, 64);
    }
}

// round 6
// speedup vs baseline: 1.5670x; 1.2548x over previous
#include <cuda_runtime.h>
#include <cstdint>

// ---------------------------------------------------------------------------
// Sparse CNN backbone, fp32, SoA (channel-major) feature layout [C][n].
// in_map[k] is monotone in the output row index -> per-channel gathers are
// nearly-contiguous LDG.32 (1-2 wavefronts) instead of 32-line scatters.
// Conv: thread = 2 rows x SLICE out-channels, tap weights staged in smem.
// ---------------------------------------------------------------------------

#define MAXN2 80000
#define MAXN4 13824

__device__ float g_xc[MAXN2 * 32];   // SoA residual/current (enc1)
__device__ float g_z1[MAXN2 * 32];
__device__ float g_z2[MAXN2 * 32];
__device__ float g_xt[MAXN2 * 32];
__device__ float g_y[MAXN4 * 64];    // SoA current (enc2)
__device__ float g_part[1024 * 64 * 2];
__device__ float g_par[128];

typedef unsigned long long ull;

__device__ __forceinline__ ull pack2(float x) {
    ull r;
    asm("mov.b64 %0, {%1, %1};" : "=l"(r) : "f"(x));
    return r;
}
__device__ __forceinline__ void fma2(ull& d, ull a, ull b) {
    asm("fma.rn.f32x2 %0, %1, %2, %0;" : "+l"(d) : "l"(a), "l"(b));
}

// ---------------------------------------------------------------------------
// SoA conv. featsT [CIN][n_in], outT [COUT][n_out]. Thread handles rows
// (bx*512+tid, +256) x SLICE channels (blockIdx.y slices COUT).
// STATS: per-block per-channel (sum,sumsq) partials -> part[bx][64][2].
// ---------------------------------------------------------------------------
template <int CIN, int SLICE, bool STATS>
__global__ __launch_bounds__(256, 3) void conv_s(
    const float* __restrict__ fT, const float* __restrict__ W,
    const int* __restrict__ in_map, int n_in, int n_out, int COUT,
    float* __restrict__ oT, float* __restrict__ part) {
    extern __shared__ float sm[];
    float* sW = sm;  // [27][CIN][SLICE]
    const int tid = threadIdx.x;
    const int yoff = blockIdx.y * SLICE;
    constexpr int WV = SLICE / 4;

    for (int i = tid; i < 27 * CIN * WV; i += 256) {
        int r = i / WV, c4 = (i % WV) * 4;
        reinterpret_cast<float4*>(sW)[i] =
            *reinterpret_cast<const float4*>(W + (size_t)r * COUT + yoff + c4);
    }
    __syncthreads();

    const int r0 = blockIdx.x * 512 + tid;
    const int r1 = r0 + 256;
    const bool ok0 = r0 < n_out, ok1 = r1 < n_out;

    ull acc0[SLICE / 2], acc1[SLICE / 2];
#pragma unroll
    for (int i = 0; i < SLICE / 2; i++) { acc0[i] = 0ull; acc1[i] = 0ull; }

    int i0n = ok0 ? __ldg(&in_map[r0]) : n_in;
    int i1n = ok1 ? __ldg(&in_map[r1]) : n_in;

    for (int k = 0; k < 27; k++) {
        const int i0 = i0n, i1 = i1n;
        if (k + 1 < 27) {
            const int* mp = in_map + (size_t)(k + 1) * n_out;
            i0n = ok0 ? __ldg(&mp[r0]) : n_in;
            i1n = ok1 ? __ldg(&mp[r1]) : n_in;
        }
        const bool v0 = i0 < n_in, v1 = i1 < n_in;
        if (__ballot_sync(0xffffffffu, v0 | v1) == 0u) continue;

        const float* wk = sW + k * CIN * SLICE;
#pragma unroll
        for (int c = 0; c < CIN; c++) {
            float x0 = v0 ? __ldg(fT + (size_t)c * n_in + i0) : 0.f;
            float x1 = v1 ? __ldg(fT + (size_t)c * n_in + i1) : 0.f;
            ull a0 = pack2(x0), a1 = pack2(x1);
            const ulonglong2* wr =
                reinterpret_cast<const ulonglong2*>(wk + c * SLICE);
#pragma unroll
            for (int p = 0; p < SLICE / 4; p++) {
                ulonglong2 w = wr[p];
                fma2(acc0[2 * p], a0, w.x);
                fma2(acc0[2 * p + 1], a0, w.y);
                fma2(acc1[2 * p], a1, w.x);
                fma2(acc1[2 * p + 1], a1, w.y);
            }
        }
    }

    float v0s[SLICE], v1s[SLICE];
#pragma unroll
    for (int p = 0; p < SLICE / 2; p++) {
        float2 a = *reinterpret_cast<float2*>(&acc0[p]);
        v0s[2 * p] = a.x; v0s[2 * p + 1] = a.y;
        float2 b = *reinterpret_cast<float2*>(&acc1[p]);
        v1s[2 * p] = b.x; v1s[2 * p + 1] = b.y;
    }
    // Transposed (SoA) stores: coalesced STG.32 per channel.
#pragma unroll
    for (int s = 0; s < SLICE; s++) {
        if (ok0) oT[(size_t)(yoff + s) * n_out + r0] = v0s[s];
        if (ok1) oT[(size_t)(yoff + s) * n_out + r1] = v1s[s];
    }

    if (STATS) {
        __syncthreads();  // done with sW
        float* sv = sm;                  // 256*SLICE
        float* sq = sm + 256 * SLICE;    // 256*SLICE
#pragma unroll
        for (int s = 0; s < SLICE; s++) {
            // rows >= n_out accumulated exact zeros (all taps forced invalid)
            sv[tid * SLICE + s] = v0s[s] + v1s[s];
            sq[tid * SLICE + s] = v0s[s] * v0s[s] + v1s[s] * v1s[s];
        }
        __syncthreads();
        constexpr int P = 256 / SLICE;
        const int c = tid % SLICE, gsub = tid / SLICE;
        float S = 0.f, Q = 0.f;
        for (int r = gsub; r < 256; r += P) {
            S += sv[r * SLICE + c];
            Q += sq[r * SLICE + c];
        }
        __syncthreads();
        sv[gsub * SLICE + c] = S;
        sq[gsub * SLICE + c] = Q;
        __syncthreads();
        if (tid < SLICE) {
            float S2 = 0.f, Q2 = 0.f;
#pragma unroll
            for (int r = 0; r < P; r++) {
                S2 += sv[r * SLICE + tid];
                Q2 += sq[r * SLICE + tid];
            }
            part[((size_t)blockIdx.x * 64 + yoff + tid) * 2] = S2;
            part[((size_t)blockIdx.x * 64 + yoff + tid) * 2 + 1] = Q2;
        }
    }
}

// ---------------------------------------------------------------------------
// First conv: CIN=4 (geo ++ col), COUT=32, K=125, ReLU, SoA output.
// ---------------------------------------------------------------------------
__global__ __launch_bounds__(256, 3) void conv1_s(
    const float* __restrict__ geo, const float* __restrict__ col,
    const float* __restrict__ W, const int* __restrict__ in_map, int n_in,
    int n_out, float* __restrict__ oT) {
    extern __shared__ float sm[];
    const int tid = threadIdx.x;
    for (int i = tid; i < 125 * 32; i += 256)
        reinterpret_cast<float4*>(sm)[i] = reinterpret_cast<const float4*>(W)[i];
    __syncthreads();

    const int row = blockIdx.x * 256 + tid;
    if (row >= n_out) return;

    ull acc[16];
#pragma unroll
    for (int i = 0; i < 16; i++) acc[i] = 0ull;

    int idxn = __ldg(&in_map[row]);
    for (int k = 0; k < 125; k++) {
        int idx = idxn;
        if (k + 1 < 125) idxn = __ldg(&in_map[(size_t)(k + 1) * n_out + row]);
        if (idx >= n_in) continue;

        float fr[4];
        fr[0] = __ldg(&geo[idx]);
        fr[1] = __ldg(&col[(size_t)idx * 3]);
        fr[2] = __ldg(&col[(size_t)idx * 3 + 1]);
        fr[3] = __ldg(&col[(size_t)idx * 3 + 2]);
        const float* wk = sm + k * 128;
#pragma unroll
        for (int c = 0; c < 4; c++) {
            ull a2 = pack2(fr[c]);
            const ulonglong2* wrow = reinterpret_cast<const ulonglong2*>(wk + c * 32);
#pragma unroll
            for (int p = 0; p < 8; p++) {
                ulonglong2 w = wrow[p];
                fma2(acc[2 * p], a2, w.x);
                fma2(acc[2 * p + 1], a2, w.y);
            }
        }
    }
#pragma unroll
    for (int p = 0; p < 16; p++) {
        float2 v = *reinterpret_cast<float2*>(&acc[p]);
        oT[(size_t)(2 * p) * n_out + row] = fmaxf(v.x, 0.f);
        oT[(size_t)(2 * p + 1) * n_out + row] = fmaxf(v.y, 0.f);
    }
}

// ---------------------------------------------------------------------------
// Fold per-block partials -> scale/shift. part layout [nblk][64][2].
// ---------------------------------------------------------------------------
__global__ __launch_bounds__(256) void bn_reduce(
    const float* __restrict__ part, int nblk, int C, int n,
    const float* __restrict__ g, const float* __restrict__ b,
    float* __restrict__ params) {
    __shared__ float ss[256], sq[256];
    const int t = threadIdx.x;
    const int P = 256 / C;
    const int c = t % C, r = t / C;
    float s = 0.f, q = 0.f;
    for (int i = r; i < nblk; i += P) {
        s += part[((size_t)i * 64 + c) * 2];
        q += part[((size_t)i * 64 + c) * 2 + 1];
    }
    ss[t] = s;
    sq[t] = q;
    __syncthreads();
    for (int o = P / 2; o >= 1; o >>= 1) {
        if (r < o) {
            ss[t] += ss[t + o * C];
            sq[t] += sq[t + o * C];
        }
        __syncthreads();
    }
    if (r == 0) {
        float inv_n = 1.f / (float)n;
        float mu = ss[t] * inv_n;
        float var = sq[t] * inv_n - mu * mu;
        float sc = g[c] * rsqrtf(var + 1e-5f);
        params[c] = sc;
        params[C + c] = b[c] - mu * sc;
    }
}

// SoA: xt[c][i] = relu(z[c][i]*sc[c]+sh[c]). gridDim.y = channel.
__global__ __launch_bounds__(256) void bn_apply_s(
    const float* __restrict__ z, const float* __restrict__ par,
    float* __restrict__ out, int n, int C) {
    const int c = blockIdx.y;
    const float sc = par[c], sh = par[C + c];
    const float* zp = z + (size_t)c * n;
    float* op = out + (size_t)c * n;
    for (int i = blockIdx.x * 256 + threadIdx.x; i < n; i += gridDim.x * 256)
        op[i] = fmaxf(zp[i] * sc + sh, 0.f);
}

// SoA: out[c][i] = relu(z[c][i]*sc[c]+sh[c] + res[c][i])
__global__ __launch_bounds__(256) void bn_res_relu_s(
    const float* __restrict__ z, const float* __restrict__ par,
    const float* __restrict__ res, float* __restrict__ out, int n, int C) {
    const int c = blockIdx.y;
    const float sc = par[c], sh = par[C + c];
    const float* zp = z + (size_t)c * n;
    const float* rp = res + (size_t)c * n;
    float* op = out + (size_t)c * n;
    for (int i = blockIdx.x * 256 + threadIdx.x; i < n; i += gridDim.x * 256)
        op[i] = fmaxf(zp[i] * sc + sh + rp[i], 0.f);
}

// Final: relu(bn(z)+res) SoA -> AoS d_out, smem-tiled transpose (64 rows/blk).
__global__ __launch_bounds__(256) void final_k(
    const float* __restrict__ z, const float* __restrict__ par,
    const float* __restrict__ res, float* __restrict__ out, int n) {
    __shared__ float t[64 * 65];
    const int R0 = blockIdx.x * 64;
    const int tid = threadIdx.x;
    for (int i = tid; i < 4096; i += 256) {
        int c = i >> 6, r = i & 63;
        int row = R0 + r;
        float v = 0.f;
        if (row < n) {
            v = z[(size_t)c * n + row] * par[c] + par[64 + c] +
                res[(size_t)c * n + row];
            v = fmaxf(v, 0.f);
        }
        t[c * 65 + r] = v;
    }
    __syncthreads();
    for (int i = tid; i < 4096; i += 256) {
        int r = i >> 6, c = i & 63;
        int row = R0 + r;
        if (row < n) out[(size_t)row * 64 + c] = t[c * 65 + r];
    }
}

// ---------------------------------------------------------------------------
extern "C" void kernel_launch(void* const* d_in, const int* in_sizes, int n_in,
                              void* d_out, int out_size) {
    const float* x_geo = (const float*)d_in[0];
    const float* x_col = (const float*)d_in[1];
    const float* w0 = (const float*)d_in[2];
    const float* w_e1 = (const float*)d_in[3];
    const float* g_e1 = (const float*)d_in[4];
    const float* b_e1 = (const float*)d_in[5];
    const float* w2 = (const float*)d_in[6];
    const float* w_e2 = (const float*)d_in[7];
    const float* g_e2 = (const float*)d_in[8];
    const float* b_e2 = (const float*)d_in[9];
    const int* m1_in = (const int*)d_in[10];
    const int* m2_in = (const int*)d_in[12];
    const int* m3_in = (const int*)d_in[14];
    const int* m4_in = (const int*)d_in[16];

    const int N = in_sizes[0];
    const int n2 = in_sizes[10] / 125;
    const int n4 = in_sizes[14] / 27;

    float *xc, *z1, *z2, *xt, *yb, *part, *par;
    cudaGetSymbolAddress((void**)&xc, g_xc);
    cudaGetSymbolAddress((void**)&z1, g_z1);
    cudaGetSymbolAddress((void**)&z2, g_z2);
    cudaGetSymbolAddress((void**)&xt, g_xt);
    cudaGetSymbolAddress((void**)&yb, g_y);
    cudaGetSymbolAddress((void**)&part, g_part);
    cudaGetSymbolAddress((void**)&par, g_par);

    const int SM1 = 125 * 4 * 32 * 4;        // 64000
    const int SME1 = 27 * 32 * 16 * 4;       // 55296 (CIN32 SLICE16)
    const int SMC2 = 27 * 32 * 16 * 4;       // 55296 (CIN32 SLICE16, COUT 64)
    const int SME2 = 27 * 64 * 8 * 4;        // 55296 (CIN64 SLICE8)
    cudaFuncSetAttribute(conv1_s, cudaFuncAttributeMaxDynamicSharedMemorySize, SM1);
    cudaFuncSetAttribute(conv_s<32, 16, true>, cudaFuncAttributeMaxDynamicSharedMemorySize, SME1);
    cudaFuncSetAttribute(conv_s<32, 16, false>, cudaFuncAttributeMaxDynamicSharedMemorySize, SMC2);
    cudaFuncSetAttribute(conv_s<64, 8, true>, cudaFuncAttributeMaxDynamicSharedMemorySize, SME2);

    const int gx2 = (n2 + 511) / 512;   // conv rows/block = 512
    const int gx4 = (n4 + 511) / 512;
    const dim3 ge1(gx2, 2);             // COUT 32 / SLICE 16
    const dim3 gc2(gx4, 4);             // COUT 64 / SLICE 16
    const dim3 ge2(gx4, 8);             // COUT 64 / SLICE 8
    const dim3 ea1((n2 + 2047) / 2048, 32);
    const dim3 ea2((n4 + 2047) / 2048, 64);

    // conv1 (k5 s2, 4->32) + ReLU -> xc (SoA)
    conv1_s<<<(n2 + 255) / 256, 256, SM1>>>(x_geo, x_col, w0, m1_in, N, n2, xc);

    // enc1: 2 BasicBlocks, 32ch (all SoA)
    for (int i = 0; i < 2; i++) {
        const float* wA = w_e1 + (size_t)(i * 2 + 0) * 27 * 32 * 32;
        const float* wB = w_e1 + (size_t)(i * 2 + 1) * 27 * 32 * 32;
        conv_s<32, 16, true><<<ge1, 256, SME1>>>(xc, wA, m2_in, n2, n2, 32, z1, part);
        bn_reduce<<<1, 256>>>(part, gx2, 32, n2,
                              g_e1 + (size_t)(i * 2) * 32, b_e1 + (size_t)(i * 2) * 32, par);
        bn_apply_s<<<ea1, 256>>>(z1, par, xt, n2, 32);
        conv_s<32, 16, true><<<ge1, 256, SME1>>>(xt, wB, m2_in, n2, n2, 32, z2, part);
        bn_reduce<<<1, 256>>>(part, gx2, 32, n2,
                              g_e1 + (size_t)(i * 2 + 1) * 32, b_e1 + (size_t)(i * 2 + 1) * 32, par);
        bn_res_relu_s<<<ea1, 256>>>(z2, par, xc, xc, n2, 32);
    }

    // conv2 (32 -> 64, onto stride-4 coords) -> yb (SoA)
    conv_s<32, 16, false><<<gc2, 256, SMC2>>>(xc, w2, m3_in, n2, n4, 64, yb, nullptr);

    // enc2: 2 BasicBlocks, 64ch
    for (int i = 0; i < 2; i++) {
        const float* wA = w_e2 + (size_t)(i * 2 + 0) * 27 * 64 * 64;
        const float* wB = w_e2 + (size_t)(i * 2 + 1) * 27 * 64 * 64;
        conv_s<64, 8, true><<<ge2, 256, SME2>>>(yb, wA, m4_in, n4, n4, 64, z1, part);
        bn_reduce<<<1, 256>>>(part, gx4, 64, n4,
                              g_e2 + (size_t)(i * 2) * 64, b_e2 + (size_t)(i * 2) * 64, par);
        bn_apply_s<<<ea2, 256>>>(z1, par, xt, n4, 64);
        conv_s<64, 8, true><<<ge2, 256, SME2>>>(xt, wB, m4_in, n4, n4, 64, z2, part);
        bn_reduce<<<1, 256>>>(part, gx4, 64, n4,
                              g_e2 + (size_t)(i * 2 + 1) * 64, b_e2 + (size_t)(i * 2 + 1) * 64, par);
        if (i == 1) {
            final_k<<<(n4 + 63) / 64, 256>>>(z2, par, yb, (float*)d_out, n4);
        } else {
            bn_res_relu_s<<<ea2, 256>>>(z2, par, yb, yb, n4, 64);
        }
    }
}

// round 7
// speedup vs baseline: 1.7909x; 1.1429x over previous
#include <cuda_runtime.h>
#include <cstdint>

// ---------------------------------------------------------------------------
// Sparse CNN backbone, fp32, SoA [C][n] features. Conv: thread = 1 row x
// SLICE out-channels, all-tap weights in smem, load-then-FMA batches.
// ---------------------------------------------------------------------------

#define MAXN2 80000
#define MAXN4 13824

__device__ float g_xc[MAXN2 * 32];
__device__ float g_z1[MAXN2 * 32];
__device__ float g_z2[MAXN2 * 32];
__device__ float g_xt[MAXN2 * 32];
__device__ float g_y[MAXN4 * 64];
__device__ float g_part[1024 * 64 * 2];
__device__ float g_par[128];

typedef unsigned long long ull;

__device__ __forceinline__ ull pack2(float x) {
    ull r;
    asm("mov.b64 %0, {%1, %1};" : "=l"(r) : "f"(x));
    return r;
}
__device__ __forceinline__ void fma2(ull& d, ull a, ull b) {
    asm("fma.rn.f32x2 %0, %1, %2, %0;" : "+l"(d) : "l"(a), "l"(b));
}

// ---------------------------------------------------------------------------
// SoA conv. fT [CIN][n_in] -> oT [COUT][n_out]. Thread = 1 row x SLICE chans
// (blockIdx.y slices COUT). 256 rows per CTA. STATS: per-block per-channel
// (sum,sumsq) partials -> part[bx][64][2] (only for yoff..yoff+SLICE).
// ---------------------------------------------------------------------------
template <int CIN, int SLICE, bool STATS, int MAXB>
__global__ __launch_bounds__(256, MAXB) void conv_f(
    const float* __restrict__ fT, const float* __restrict__ W,
    const int* __restrict__ in_map, int n_in, int n_out, int COUT,
    float* __restrict__ oT, float* __restrict__ part) {
    extern __shared__ float sm[];
    float* sW = sm;  // [27][CIN][SLICE]
    const int tid = threadIdx.x;
    const int yoff = blockIdx.y * SLICE;
    constexpr int WV = SLICE / 4;

    for (int i = tid; i < 27 * CIN * WV; i += 256) {
        int r = i / WV, c4 = (i % WV) * 4;
        reinterpret_cast<float4*>(sW)[i] =
            *reinterpret_cast<const float4*>(W + (size_t)r * COUT + yoff + c4);
    }
    __syncthreads();

    const int row = blockIdx.x * 256 + tid;
    const bool rowok = row < n_out;

    ull acc[SLICE / 2];
#pragma unroll
    for (int i = 0; i < SLICE / 2; i++) acc[i] = 0ull;

    int idxn = rowok ? __ldg(&in_map[row]) : n_in;
    for (int k = 0; k < 27; k++) {
        const int idx = idxn;
        if (k + 1 < 27)
            idxn = rowok ? __ldg(&in_map[(size_t)(k + 1) * n_out + row]) : n_in;
        if (idx >= n_in) continue;

        // Batch: gather all CIN channel values (near-contiguous LDG.32)
        float x[CIN];
#pragma unroll
        for (int c = 0; c < CIN; c++) x[c] = __ldg(fT + (size_t)c * n_in + idx);

        const float* wk = sW + k * CIN * SLICE;
#pragma unroll
        for (int c = 0; c < CIN; c++) {
            ull a2 = pack2(x[c]);
            const ulonglong2* wr =
                reinterpret_cast<const ulonglong2*>(wk + c * SLICE);
#pragma unroll
            for (int p = 0; p < SLICE / 4; p++) {
                ulonglong2 w = wr[p];
                fma2(acc[2 * p], a2, w.x);
                fma2(acc[2 * p + 1], a2, w.y);
            }
        }
    }

    float res[SLICE];
#pragma unroll
    for (int p = 0; p < SLICE / 2; p++) {
        float2 v = *reinterpret_cast<float2*>(&acc[p]);
        res[2 * p] = v.x;
        res[2 * p + 1] = v.y;
    }
    if (rowok) {
#pragma unroll
        for (int s = 0; s < SLICE; s++)
            oT[(size_t)(yoff + s) * n_out + row] = res[s];
    }

    if (STATS) {
        __syncthreads();  // done with sW
        float* sv = sm;                  // 256*SLICE
        float* sq = sm + 256 * SLICE;    // 256*SLICE
#pragma unroll
        for (int s = 0; s < SLICE; s++) {
            float v = rowok ? res[s] : 0.f;
            sv[tid * SLICE + s] = v;
            sq[tid * SLICE + s] = v * v;
        }
        __syncthreads();
        constexpr int P = 256 / SLICE;
        const int c = tid % SLICE, gsub = tid / SLICE;
        float S = 0.f, Q = 0.f;
        for (int r = gsub; r < 256; r += P) {
            S += sv[r * SLICE + c];
            Q += sq[r * SLICE + c];
        }
        __syncthreads();
        sv[gsub * SLICE + c] = S;
        sq[gsub * SLICE + c] = Q;
        __syncthreads();
        if (tid < SLICE) {
            float S2 = 0.f, Q2 = 0.f;
#pragma unroll
            for (int r = 0; r < P; r++) {
                S2 += sv[r * SLICE + tid];
                Q2 += sq[r * SLICE + tid];
            }
            part[((size_t)blockIdx.x * 64 + yoff + tid) * 2] = S2;
            part[((size_t)blockIdx.x * 64 + yoff + tid) * 2 + 1] = Q2;
        }
    }
}

// ---------------------------------------------------------------------------
// First conv: CIN=4 (geo ++ col), COUT=32, K=125, ReLU, SoA output.
// ---------------------------------------------------------------------------
__global__ __launch_bounds__(256, 3) void conv1_s(
    const float* __restrict__ geo, const float* __restrict__ col,
    const float* __restrict__ W, const int* __restrict__ in_map, int n_in,
    int n_out, float* __restrict__ oT) {
    extern __shared__ float sm[];
    const int tid = threadIdx.x;
    for (int i = tid; i < 125 * 32; i += 256)
        reinterpret_cast<float4*>(sm)[i] = reinterpret_cast<const float4*>(W)[i];
    __syncthreads();

    const int row = blockIdx.x * 256 + tid;
    if (row >= n_out) return;

    ull acc[16];
#pragma unroll
    for (int i = 0; i < 16; i++) acc[i] = 0ull;

    int idxn = __ldg(&in_map[row]);
    for (int k = 0; k < 125; k++) {
        int idx = idxn;
        if (k + 1 < 125) idxn = __ldg(&in_map[(size_t)(k + 1) * n_out + row]);
        if (idx >= n_in) continue;

        float fr[4];
        fr[0] = __ldg(&geo[idx]);
        fr[1] = __ldg(&col[(size_t)idx * 3]);
        fr[2] = __ldg(&col[(size_t)idx * 3 + 1]);
        fr[3] = __ldg(&col[(size_t)idx * 3 + 2]);
        const float* wk = sm + k * 128;
#pragma unroll
        for (int c = 0; c < 4; c++) {
            ull a2 = pack2(fr[c]);
            const ulonglong2* wrow = reinterpret_cast<const ulonglong2*>(wk + c * 32);
#pragma unroll
            for (int p = 0; p < 8; p++) {
                ulonglong2 w = wrow[p];
                fma2(acc[2 * p], a2, w.x);
                fma2(acc[2 * p + 1], a2, w.y);
            }
        }
    }
#pragma unroll
    for (int p = 0; p < 16; p++) {
        float2 v = *reinterpret_cast<float2*>(&acc[p]);
        oT[(size_t)(2 * p) * n_out + row] = fmaxf(v.x, 0.f);
        oT[(size_t)(2 * p + 1) * n_out + row] = fmaxf(v.y, 0.f);
    }
}

// ---------------------------------------------------------------------------
__global__ __launch_bounds__(256) void bn_reduce(
    const float* __restrict__ part, int nblk, int C, int n,
    const float* __restrict__ g, const float* __restrict__ b,
    float* __restrict__ params) {
    __shared__ float ss[256], sq[256];
    const int t = threadIdx.x;
    const int P = 256 / C;
    const int c = t % C, r = t / C;
    float s = 0.f, q = 0.f;
    for (int i = r; i < nblk; i += P) {
        s += part[((size_t)i * 64 + c) * 2];
        q += part[((size_t)i * 64 + c) * 2 + 1];
    }
    ss[t] = s;
    sq[t] = q;
    __syncthreads();
    for (int o = P / 2; o >= 1; o >>= 1) {
        if (r < o) {
            ss[t] += ss[t + o * C];
            sq[t] += sq[t + o * C];
        }
        __syncthreads();
    }
    if (r == 0) {
        float inv_n = 1.f / (float)n;
        float mu = ss[t] * inv_n;
        float var = sq[t] * inv_n - mu * mu;
        float sc = g[c] * rsqrtf(var + 1e-5f);
        params[c] = sc;
        params[C + c] = b[c] - mu * sc;
    }
}

// SoA: out[c][i] = relu(z[c][i]*sc[c]+sh[c])
__global__ __launch_bounds__(256) void bn_apply_s(
    const float* __restrict__ z, const float* __restrict__ par,
    float* __restrict__ out, int n, int C) {
    const int c = blockIdx.y;
    const float sc = par[c], sh = par[C + c];
    const float* zp = z + (size_t)c * n;
    float* op = out + (size_t)c * n;
    for (int i = blockIdx.x * 256 + threadIdx.x; i < n; i += gridDim.x * 256)
        op[i] = fmaxf(zp[i] * sc + sh, 0.f);
}

// SoA: out[c][i] = relu(z[c][i]*sc[c]+sh[c] + res[c][i])
__global__ __launch_bounds__(256) void bn_res_relu_s(
    const float* __restrict__ z, const float* __restrict__ par,
    const float* __restrict__ res, float* __restrict__ out, int n, int C) {
    const int c = blockIdx.y;
    const float sc = par[c], sh = par[C + c];
    const float* zp = z + (size_t)c * n;
    const float* rp = res + (size_t)c * n;
    float* op = out + (size_t)c * n;
    for (int i = blockIdx.x * 256 + threadIdx.x; i < n; i += gridDim.x * 256)
        op[i] = fmaxf(zp[i] * sc + sh + rp[i], 0.f);
}

// Final: relu(bn(z)+res) SoA -> AoS d_out, smem-tiled transpose.
__global__ __launch_bounds__(256) void final_k(
    const float* __restrict__ z, const float* __restrict__ par,
    const float* __restrict__ res, float* __restrict__ out, int n) {
    __shared__ float t[64 * 65];
    const int R0 = blockIdx.x * 64;
    const int tid = threadIdx.x;
    for (int i = tid; i < 4096; i += 256) {
        int c = i >> 6, r = i & 63;
        int row = R0 + r;
        float v = 0.f;
        if (row < n) {
            v = z[(size_t)c * n + row] * par[c] + par[64 + c] +
                res[(size_t)c * n + row];
            v = fmaxf(v, 0.f);
        }
        t[c * 65 + r] = v;
    }
    __syncthreads();
    for (int i = tid; i < 4096; i += 256) {
        int r = i >> 6, c = i & 63;
        int row = R0 + r;
        if (row < n) out[(size_t)row * 64 + c] = t[c * 65 + r];
    }
}

// ---------------------------------------------------------------------------
extern "C" void kernel_launch(void* const* d_in, const int* in_sizes, int n_in,
                              void* d_out, int out_size) {
    const float* x_geo = (const float*)d_in[0];
    const float* x_col = (const float*)d_in[1];
    const float* w0 = (const float*)d_in[2];
    const float* w_e1 = (const float*)d_in[3];
    const float* g_e1 = (const float*)d_in[4];
    const float* b_e1 = (const float*)d_in[5];
    const float* w2 = (const float*)d_in[6];
    const float* w_e2 = (const float*)d_in[7];
    const float* g_e2 = (const float*)d_in[8];
    const float* b_e2 = (const float*)d_in[9];
    const int* m1_in = (const int*)d_in[10];
    const int* m2_in = (const int*)d_in[12];
    const int* m3_in = (const int*)d_in[14];
    const int* m4_in = (const int*)d_in[16];

    const int N = in_sizes[0];
    const int n2 = in_sizes[10] / 125;
    const int n4 = in_sizes[14] / 27;

    float *xc, *z1, *z2, *xt, *yb, *part, *par;
    cudaGetSymbolAddress((void**)&xc, g_xc);
    cudaGetSymbolAddress((void**)&z1, g_z1);
    cudaGetSymbolAddress((void**)&z2, g_z2);
    cudaGetSymbolAddress((void**)&xt, g_xt);
    cudaGetSymbolAddress((void**)&yb, g_y);
    cudaGetSymbolAddress((void**)&part, g_part);
    cudaGetSymbolAddress((void**)&par, g_par);

    const int SM1 = 125 * 4 * 32 * 4;        // 64000
    const int SME1 = 27 * 32 * 32 * 4;       // 110592 (CIN32, full COUT32)
    const int SMC2 = 27 * 32 * 16 * 4;       // 55296  (CIN32, SLICE16)
    const int SME2 = 27 * 64 * 16 * 4;       // 110592 (CIN64, SLICE16)
    cudaFuncSetAttribute(conv1_s, cudaFuncAttributeMaxDynamicSharedMemorySize, SM1);
    cudaFuncSetAttribute(conv_f<32, 32, true, 2>, cudaFuncAttributeMaxDynamicSharedMemorySize, SME1);
    cudaFuncSetAttribute(conv_f<32, 16, false, 3>, cudaFuncAttributeMaxDynamicSharedMemorySize, SMC2);
    cudaFuncSetAttribute(conv_f<64, 16, true, 2>, cudaFuncAttributeMaxDynamicSharedMemorySize, SME2);

    const int gx2 = (n2 + 255) / 256;   // 256 rows per CTA
    const int gx4 = (n4 + 255) / 256;
    const dim3 ge1(gx2, 1);             // full COUT 32
    const dim3 gc2(gx4, 4);             // COUT 64, SLICE 16
    const dim3 ge2(gx4, 4);             // COUT 64, SLICE 16
    const dim3 ea1((n2 + 2047) / 2048, 32);
    const dim3 ea2((n4 + 2047) / 2048, 64);

    // conv1 (k5 s2, 4->32) + ReLU -> xc (SoA)
    conv1_s<<<gx2, 256, SM1>>>(x_geo, x_col, w0, m1_in, N, n2, xc);

    // enc1: 2 BasicBlocks, 32ch
    for (int i = 0; i < 2; i++) {
        const float* wA = w_e1 + (size_t)(i * 2 + 0) * 27 * 32 * 32;
        const float* wB = w_e1 + (size_t)(i * 2 + 1) * 27 * 32 * 32;
        conv_f<32, 32, true, 2><<<ge1, 256, SME1>>>(xc, wA, m2_in, n2, n2, 32, z1, part);
        bn_reduce<<<1, 256>>>(part, gx2, 32, n2,
                              g_e1 + (size_t)(i * 2) * 32, b_e1 + (size_t)(i * 2) * 32, par);
        bn_apply_s<<<ea1, 256>>>(z1, par, xt, n2, 32);
        conv_f<32, 32, true, 2><<<ge1, 256, SME1>>>(xt, wB, m2_in, n2, n2, 32, z2, part);
        bn_reduce<<<1, 256>>>(part, gx2, 32, n2,
                              g_e1 + (size_t)(i * 2 + 1) * 32, b_e1 + (size_t)(i * 2 + 1) * 32, par);
        bn_res_relu_s<<<ea1, 256>>>(z2, par, xc, xc, n2, 32);
    }

    // conv2 (32 -> 64, onto stride-4 coords) -> yb (SoA)
    conv_f<32, 16, false, 3><<<gc2, 256, SMC2>>>(xc, w2, m3_in, n2, n4, 64, yb, nullptr);

    // enc2: 2 BasicBlocks, 64ch
    for (int i = 0; i < 2; i++) {
        const float* wA = w_e2 + (size_t)(i * 2 + 0) * 27 * 64 * 64;
        const float* wB = w_e2 + (size_t)(i * 2 + 1) * 27 * 64 * 64;
        conv_f<64, 16, true, 2><<<ge2, 256, SME2>>>(yb, wA, m4_in, n4, n4, 64, z1, part);
        bn_reduce<<<1, 256>>>(part, gx4, 64, n4,
                              g_e2 + (size_t)(i * 2) * 64, b_e2 + (size_t)(i * 2) * 64, par);
        bn_apply_s<<<ea2, 256>>>(z1, par, xt, n4, 64);
        conv_f<64, 16, true, 2><<<ge2, 256, SME2>>>(xt, wB, m4_in, n4, n4, 64, z2, part);
        bn_reduce<<<1, 256>>>(part, gx4, 64, n4,
                              g_e2 + (size_t)(i * 2 + 1) * 64, b_e2 + (size_t)(i * 2 + 1) * 64, par);
        if (i == 1) {
            final_k<<<(n4 + 63) / 64, 256>>>(z2, par, yb, (float*)d_out, n4);
        } else {
            bn_res_relu_s<<<ea2, 256>>>(z2, par, yb, yb, n4, 64);
        }
    }
}